// round 3
// baseline (speedup 1.0000x reference)
#include <cuda_runtime.h>
#include <cuda_bf16.h>
#include <cstdint>

// Problem constants
#define TSEQ 1024
#define BATCH 64
#define HID 128
#define G4 512            // 4*HID
#define XGHALF (TSEQ*BATCH*G4)   // per-direction xg elements

typedef unsigned long long ull;

// ---------------- scratch (static device globals; no allocations) -------------
__device__ float g_xt[TSEQ * BATCH * 128];        // x transposed to [T,B,128]
__device__ float g_xg[2 * TSEQ * BATCH * G4];     // [dir][T][B][512]
__device__ float g_out1[TSEQ * BATCH * 256];      // layer-1 output [T,B,256]

// ---------------- fast activations -------------------------------------------
__device__ __forceinline__ float fsig(float x) {
    return 1.0f / (1.0f + __expf(-x));
}
__device__ __forceinline__ float ftanh_(float x) {
    return 2.0f * fsig(2.0f * x) - 1.0f;
}

// ---------------- packed f32x2 helpers ----------------------------------------
__device__ __forceinline__ void ffma2(ull& acc, ull a, ull b) {
    asm volatile("fma.rn.f32x2 %0, %1, %2, %0;" : "+l"(acc) : "l"(a), "l"(b));
}
__device__ __forceinline__ ull pack2(float lo, float hi) {
    ull r;
    asm("mov.b64 %0, {%1, %2};" : "=l"(r) : "f"(lo), "f"(hi));
    return r;
}
__device__ __forceinline__ float2 unpack2(ull v) {
    float2 r;
    asm("mov.b64 {%0, %1}, %2;" : "=f"(r.x), "=f"(r.y) : "l"(v));
    return r;
}

// ---------------- transpose x: [B,T,128] -> [T,B,128] -------------------------
__global__ void transpose_x(const float4* __restrict__ x, float4* __restrict__ xt) {
    int i = blockIdx.x * blockDim.x + threadIdx.x;   // over T*B*32 float4s
    if (i >= TSEQ * BATCH * 32) return;
    int t  = i >> 11;          // / (64*32)
    int r  = i & 2047;
    int b  = r >> 5;
    int k4 = r & 31;
    xt[i] = x[((size_t)b * TSEQ + t) * 32 + k4];
}

// ---------------- SGEMM (f32x2): C[M,N] = A[M,K]*B[N,K]^T + bias1[n]+bias2[n] -
// BM=64, BN=128, BK=16, 256 threads, 4(m)x8(n) per thread via packed FFMA2.
#define BM 64
#define BN 128
#define BKK 16
__global__ __launch_bounds__(256) void sgemm_bias(
    const float* __restrict__ A, const float* __restrict__ B,
    const float* __restrict__ bias1, const float* __restrict__ bias2,
    float* __restrict__ C, int M, int N, int K)
{
    __shared__ float As[BKK][BM + 4];    // 68-f rows (16B aligned)
    __shared__ float Bs[BKK][BN + 4];    // 132-f rows (16B aligned)

    int tid = threadIdx.x;
    int tx = tid & 15;       // n-group 0..15
    int ty = tid >> 4;       // m-group 0..15
    int block_m = blockIdx.x * BM;
    int block_n = blockIdx.y * BN;

    int lr = tid >> 2;               // 0..63 load row
    int lc = (tid & 3) * 4;          // 0,4,8,12 load col (k)

    const float* Ap  = A + (size_t)(block_m + lr) * K + lc;
    const float* Bp0 = B + (size_t)(block_n + lr) * K + lc;
    const float* Bp1 = B + (size_t)(block_n + 64 + lr) * K + lc;

    ull acc[4][4];
#pragma unroll
    for (int i = 0; i < 4; i++)
#pragma unroll
        for (int p = 0; p < 4; p++) acc[i][p] = 0ull;

    float4 av  = *(const float4*)Ap;
    float4 bv0 = *(const float4*)Bp0;
    float4 bv1 = *(const float4*)Bp1;

    for (int k0 = 0; k0 < K; k0 += BKK) {
        As[lc + 0][lr] = av.x;  As[lc + 1][lr] = av.y;
        As[lc + 2][lr] = av.z;  As[lc + 3][lr] = av.w;
        Bs[lc + 0][lr] = bv0.x; Bs[lc + 1][lr] = bv0.y;
        Bs[lc + 2][lr] = bv0.z; Bs[lc + 3][lr] = bv0.w;
        Bs[lc + 0][lr + 64] = bv1.x; Bs[lc + 1][lr + 64] = bv1.y;
        Bs[lc + 2][lr + 64] = bv1.z; Bs[lc + 3][lr + 64] = bv1.w;
        __syncthreads();

        if (k0 + BKK < K) {             // prefetch next tile (hidden under FMAs)
            av  = *(const float4*)(Ap  + k0 + BKK);
            bv0 = *(const float4*)(Bp0 + k0 + BKK);
            bv1 = *(const float4*)(Bp1 + k0 + BKK);
        }

#pragma unroll
        for (int k = 0; k < BKK; k++) {
            float4 a = *(const float4*)&As[k][ty * 4];
            ulonglong2 b01 = *(const ulonglong2*)&Bs[k][tx * 8];
            ulonglong2 b23 = *(const ulonglong2*)&Bs[k][tx * 8 + 4];
            ull a0 = pack2(a.x, a.x);
            ull a1 = pack2(a.y, a.y);
            ull a2 = pack2(a.z, a.z);
            ull a3 = pack2(a.w, a.w);
            ffma2(acc[0][0], a0, b01.x); ffma2(acc[0][1], a0, b01.y);
            ffma2(acc[0][2], a0, b23.x); ffma2(acc[0][3], a0, b23.y);
            ffma2(acc[1][0], a1, b01.x); ffma2(acc[1][1], a1, b01.y);
            ffma2(acc[1][2], a1, b23.x); ffma2(acc[1][3], a1, b23.y);
            ffma2(acc[2][0], a2, b01.x); ffma2(acc[2][1], a2, b01.y);
            ffma2(acc[2][2], a2, b23.x); ffma2(acc[2][3], a2, b23.y);
            ffma2(acc[3][0], a3, b01.x); ffma2(acc[3][1], a3, b01.y);
            ffma2(acc[3][2], a3, b23.x); ffma2(acc[3][3], a3, b23.y);
        }
        __syncthreads();
    }

    // bias sums for this thread's 8 columns
    int nb = block_n + tx * 8;
    float bsum[8];
#pragma unroll
    for (int u = 0; u < 8; u++)
        bsum[u] = __ldg(&bias1[nb + u]) + __ldg(&bias2[nb + u]);

#pragma unroll
    for (int i = 0; i < 4; i++) {
        size_t row = (size_t)(block_m + ty * 4 + i);
        float out[8];
#pragma unroll
        for (int p = 0; p < 4; p++) {
            float2 v = unpack2(acc[i][p]);
            out[2 * p]     = v.x + bsum[2 * p];
            out[2 * p + 1] = v.y + bsum[2 * p + 1];
        }
        float* Cp = C + row * N + nb;
        *(float4*)Cp       = make_float4(out[0], out[1], out[2], out[3]);
        *(float4*)(Cp + 4) = make_float4(out[4], out[5], out[6], out[7]);
    }
}

// ---------------- recurrent LSTM scan: one CTA per (batch, direction) ---------
// 512 threads; thread j owns gate row j (gate = j>>7 in {i,f,g,o}).
// Whh row j: cols 0..63 in registers (packed f32x2 pairs), cols 64..127 in smem
// as float4 quads transposed [quad][j] (conflict-free LDS.128).
#define RK 64
#define REC_SMEM_FLOATS (RK * G4 + HID + G4)
#define REC_SMEM_BYTES (REC_SMEM_FLOATS * 4)

__global__ __launch_bounds__(512, 1) void lstm_rec(
    const float* __restrict__ xg,        // [dir][T][B][512]
    const float* __restrict__ Whh0,      // fw weights [512][128]
    const float* __restrict__ Whh1,      // bw weights [512][128]
    float* __restrict__ out,             // h output
    int outT, int outB)                  // strides (floats) for t and b
{
    extern __shared__ float sm[];
    float4* ws4 = (float4*)sm;                   // 16*512 float4 (cols 64..127)
    float* hs = sm + RK * G4;                    // 128 (16B aligned)
    float* gs = hs + HID;                        // 512

    int j   = threadIdx.x;
    int b   = blockIdx.x;
    int dir = blockIdx.y;
    const float* Whh = dir ? Whh1 : Whh0;

    const float4* Wr4 = (const float4*)(Whh + (size_t)j * 128);
    // cols 0..63 -> packed register pairs
    ull wr[32];
#pragma unroll
    for (int k4 = 0; k4 < 16; k4++) {
        float4 v = Wr4[k4];
        wr[2 * k4]     = pack2(v.x, v.y);
        wr[2 * k4 + 1] = pack2(v.z, v.w);
    }
    // cols 64..127 -> smem quads, transposed: ws4[q*512 + j]
#pragma unroll
    for (int k4 = 16; k4 < 32; k4++)
        ws4[(k4 - 16) * G4 + j] = Wr4[k4];

    if (j < HID) hs[j] = 0.f;
    float c = 0.f;
    __syncthreads();

    const ulonglong2* hsp = (const ulonglong2*)hs;   // 32 x (2 packed pairs)
    const ulonglong2* wsp = (const ulonglong2*)sm;
    size_t xg_base = (size_t)dir * XGHALF + (size_t)b * G4 + j;
    int t0 = dir ? (TSEQ - 1) : 0;
    float xgv = __ldg(xg + xg_base + (size_t)t0 * (BATCH * G4));
    float* outp = out + dir * HID;
    int gate = j >> 7;                       // 0:i 1:f 2:g 3:o

    for (int s = 0; s < TSEQ; s++) {
        int t = dir ? (TSEQ - 1 - s) : s;
        // prefetch next timestep's xg (clamped; hidden under the dot product)
        int tn = dir ? max(t - 1, 0) : min(t + 1, TSEQ - 1);
        float xgn = __ldg(xg + xg_base + (size_t)tn * (BATCH * G4));

        ull acc0 = pack2(xgv, 0.f), acc1 = 0ull, acc2 = 0ull, acc3 = 0ull;
#pragma unroll
        for (int q = 0; q < 16; q++) {           // register half: k = 4q..4q+3
            ulonglong2 hp = hsp[q];
            ffma2(acc0, wr[2 * q],     hp.x);
            ffma2(acc1, wr[2 * q + 1], hp.y);
        }
#pragma unroll
        for (int q = 0; q < 16; q++) {           // smem half: k = 64+4q..
            ulonglong2 hp = hsp[16 + q];
            ulonglong2 wv = wsp[q * G4 + j];
            ffma2(acc2, wv.x, hp.x);
            ffma2(acc3, wv.y, hp.y);
        }
        float2 s0 = unpack2(acc0), s1 = unpack2(acc1);
        float2 s2 = unpack2(acc2), s3 = unpack2(acc3);
        float pre = ((s0.x + s0.y) + (s1.x + s1.y)) +
                    ((s2.x + s2.y) + (s3.x + s3.y));

        float v = (gate == 2) ? ftanh_(pre) : fsig(pre);
        gs[j] = v;
        __syncthreads();

        if (j < HID) {
            float iv = gs[j];
            float fv = gs[j + HID];
            float gv = gs[j + 2 * HID];
            float ov = gs[j + 3 * HID];
            c = fv * c + iv * gv;
            float h = ov * ftanh_(c);
            hs[j] = h;
            outp[(size_t)t * outT + (size_t)b * outB + j] = h;
        }
        __syncthreads();
        xgv = xgn;
    }
}

// ---------------- launch ------------------------------------------------------
extern "C" void kernel_launch(void* const* d_in, const int* in_sizes, int n_in,
                              void* d_out, int out_size)
{
    const float* x        = (const float*)d_in[0];
    // d_in[1] = lengths (unused, as in the reference)
    const float* Wih_fw1  = (const float*)d_in[2];
    const float* Whh_fw1  = (const float*)d_in[3];
    const float* bih_fw1  = (const float*)d_in[4];
    const float* bhh_fw1  = (const float*)d_in[5];
    const float* Wih_bw1  = (const float*)d_in[6];
    const float* Whh_bw1  = (const float*)d_in[7];
    const float* bih_bw1  = (const float*)d_in[8];
    const float* bhh_bw1  = (const float*)d_in[9];
    const float* Wih_fw2  = (const float*)d_in[10];
    const float* Whh_fw2  = (const float*)d_in[11];
    const float* bih_fw2  = (const float*)d_in[12];
    const float* bhh_fw2  = (const float*)d_in[13];
    const float* Wih_bw2  = (const float*)d_in[14];
    const float* Whh_bw2  = (const float*)d_in[15];
    const float* bih_bw2  = (const float*)d_in[16];
    const float* bhh_bw2  = (const float*)d_in[17];
    float* out = (float*)d_out;

    float *xt, *xg, *out1;
    cudaGetSymbolAddress((void**)&xt,   g_xt);
    cudaGetSymbolAddress((void**)&xg,   g_xg);
    cudaGetSymbolAddress((void**)&out1, g_out1);

    cudaFuncSetAttribute(lstm_rec, cudaFuncAttributeMaxDynamicSharedMemorySize,
                         REC_SMEM_BYTES);

    const int M = TSEQ * BATCH;          // 65536

    // 1) transpose x -> [T,B,128]
    transpose_x<<<(TSEQ * BATCH * 32 + 255) / 256, 256>>>(
        (const float4*)x, (float4*)xt);

    // 2) layer-1 input projections (bias = bih + bhh folded in)
    dim3 gg(M / BM, G4 / BN);
    sgemm_bias<<<gg, 256>>>(xt, Wih_fw1, bih_fw1, bhh_fw1, xg,          M, G4, 128);
    sgemm_bias<<<gg, 256>>>(xt, Wih_bw1, bih_bw1, bhh_bw1, xg + XGHALF, M, G4, 128);

    // 3) layer-1 recurrence -> out1 [T,B,256]
    lstm_rec<<<dim3(BATCH, 2), 512, REC_SMEM_BYTES>>>(
        xg, Whh_fw1, Whh_bw1, out1, BATCH * 256, 256);

    // 4) layer-2 input projections (K = 256)
    sgemm_bias<<<gg, 256>>>(out1, Wih_fw2, bih_fw2, bhh_fw2, xg,          M, G4, 256);
    sgemm_bias<<<gg, 256>>>(out1, Wih_bw2, bih_bw2, bhh_bw2, xg + XGHALF, M, G4, 256);

    // 5) layer-2 recurrence -> d_out [B,T,256]
    lstm_rec<<<dim3(BATCH, 2), 512, REC_SMEM_BYTES>>>(
        xg, Whh_fw2, Whh_bw2, out, 256, TSEQ * 256);
}

// round 4
// speedup vs baseline: 1.0805x; 1.0805x over previous
#include <cuda_runtime.h>
#include <cuda_bf16.h>
#include <cstdint>

// Problem constants
#define TSEQ 1024
#define BATCH 64
#define HID 128
#define G4 512            // 4*HID
#define XGHALF (TSEQ*BATCH*G4)   // per-direction xg elements

// ---------------- scratch (static device globals; no allocations) -------------
__device__ float g_xt[TSEQ * BATCH * 128];        // x transposed to [T,B,128]
__device__ float g_xg[2 * TSEQ * BATCH * G4];     // [dir][T][B][512]
__device__ float g_out1[TSEQ * BATCH * 256];      // layer-1 output [T,B,256]

// ---------------- fast activations -------------------------------------------
__device__ __forceinline__ float fsig(float x) {
    return 1.0f / (1.0f + __expf(-x));
}
__device__ __forceinline__ float ftanh_(float x) {
    return 2.0f * fsig(2.0f * x) - 1.0f;
}

// ---------------- transpose x: [B,T,128] -> [T,B,128] -------------------------
__global__ void transpose_x(const float4* __restrict__ x, float4* __restrict__ xt) {
    int i = blockIdx.x * blockDim.x + threadIdx.x;   // over T*B*32 float4s
    if (i >= TSEQ * BATCH * 32) return;
    int t  = i >> 11;          // / (64*32)
    int r  = i & 2047;
    int b  = r >> 5;
    int k4 = r & 31;
    xt[i] = x[((size_t)b * TSEQ + t) * 32 + k4];
}

// ---------------- SGEMM: C[M,N] = A[M,K] * B[N,K]^T + bias1[n] + bias2[n] -----
// (R2 version — measured at the fp32 FFMA roofline; do not touch.)
// BM=64, BN=64, BK=16, 256 threads, 4x4 per thread.
#define BM 64
#define BN 64
#define BKK 16
__global__ __launch_bounds__(256) void sgemm_bias(
    const float* __restrict__ A, const float* __restrict__ B,
    const float* __restrict__ bias1, const float* __restrict__ bias2,
    float* __restrict__ C, int M, int N, int K)
{
    __shared__ float As[BKK][BM + 4];
    __shared__ float Bs[BKK][BN + 4];

    int tid = threadIdx.x;
    int tx = tid & 15;       // 0..15
    int ty = tid >> 4;       // 0..15
    int block_m = blockIdx.x * BM;
    int block_n = blockIdx.y * BN;

    int lr = tid >> 2;               // 0..63 load row
    int lc = (tid & 3) * 4;          // 0,4,8,12 load col (k)

    const float* Ab = A + (size_t)(block_m + lr) * K + lc;
    const float* Bb = B + (size_t)(block_n + lr) * K + lc;

    float acc[4][4];
#pragma unroll
    for (int i = 0; i < 4; i++)
#pragma unroll
        for (int jj = 0; jj < 4; jj++) acc[i][jj] = 0.f;

    for (int k0 = 0; k0 < K; k0 += BKK) {
        float4 av = *(const float4*)(Ab + k0);
        float4 bv = *(const float4*)(Bb + k0);
        As[lc + 0][lr] = av.x; As[lc + 1][lr] = av.y;
        As[lc + 2][lr] = av.z; As[lc + 3][lr] = av.w;
        Bs[lc + 0][lr] = bv.x; Bs[lc + 1][lr] = bv.y;
        Bs[lc + 2][lr] = bv.z; Bs[lc + 3][lr] = bv.w;
        __syncthreads();
#pragma unroll
        for (int k = 0; k < BKK; k++) {
            float4 a = *(const float4*)&As[k][ty * 4];
            float4 b = *(const float4*)&Bs[k][tx * 4];
            acc[0][0] += a.x * b.x; acc[0][1] += a.x * b.y;
            acc[0][2] += a.x * b.z; acc[0][3] += a.x * b.w;
            acc[1][0] += a.y * b.x; acc[1][1] += a.y * b.y;
            acc[1][2] += a.y * b.z; acc[1][3] += a.y * b.w;
            acc[2][0] += a.z * b.x; acc[2][1] += a.z * b.y;
            acc[2][2] += a.z * b.z; acc[2][3] += a.z * b.w;
            acc[3][0] += a.w * b.x; acc[3][1] += a.w * b.y;
            acc[3][2] += a.w * b.z; acc[3][3] += a.w * b.w;
        }
        __syncthreads();
    }

#pragma unroll
    for (int i = 0; i < 4; i++) {
        size_t row = (size_t)(block_m + ty * 4 + i);
#pragma unroll
        for (int jj = 0; jj < 4; jj++) {
            int n = block_n + tx * 4 + jj;
            C[row * N + n] = acc[i][jj] + __ldg(&bias1[n]) + __ldg(&bias2[n]);
        }
    }
}

// ---------------- recurrent LSTM scan: one CTA per (batch, direction) ---------
// 512 threads; thread j owns gate row j (gate = j>>7 in {i,f,g,o}).
// Whh row j: cols 0..RK-1 in registers (fp32), cols RK..127 in smem
// as float4 quads transposed [quad][j] (conflict-free LDS.128).
#define RK 80
#define SKQ ((128 - RK) / 4)           // 12 smem quads per row
#define REC_SMEM_FLOATS ((128 - RK) * G4 + HID + G4)
#define REC_SMEM_BYTES (REC_SMEM_FLOATS * 4)

__global__ __launch_bounds__(512, 1) void lstm_rec(
    const float* __restrict__ xg,        // [dir][T][B][512]
    const float* __restrict__ Whh0,      // fw weights [512][128]
    const float* __restrict__ Whh1,      // bw weights [512][128]
    float* __restrict__ out,             // h output
    int outT, int outB)                  // strides (floats) for t and b
{
    extern __shared__ float sm[];
    float4* ws4 = (float4*)sm;                   // SKQ*512 float4 (cols RK..127)
    float* hs = sm + (128 - RK) * G4;            // 128 (16B aligned)
    float* gs = hs + HID;                        // 512

    int j   = threadIdx.x;
    int b   = blockIdx.x;
    int dir = blockIdx.y;
    const float* Whh = dir ? Whh1 : Whh0;

    const float4* Wr4 = (const float4*)(Whh + (size_t)j * 128);
    // cols 0..RK-1 -> registers
    float w[RK];
#pragma unroll
    for (int k4 = 0; k4 < RK / 4; k4++) {
        float4 v = Wr4[k4];
        w[4 * k4 + 0] = v.x; w[4 * k4 + 1] = v.y;
        w[4 * k4 + 2] = v.z; w[4 * k4 + 3] = v.w;
    }
    // cols RK..127 -> smem quads, transposed: ws4[q*512 + j]
#pragma unroll
    for (int q = 0; q < SKQ; q++)
        ws4[q * G4 + j] = Wr4[RK / 4 + q];

    if (j < HID) hs[j] = 0.f;
    float c = 0.f;
    __syncthreads();

    const float4* hs4 = (const float4*)hs;
    size_t xg_base = (size_t)dir * XGHALF + (size_t)b * G4 + j;
    int t0 = dir ? (TSEQ - 1) : 0;
    float xgv = __ldg(xg + xg_base + (size_t)t0 * (BATCH * G4));
    float* outp = out + dir * HID;
    int gate = j >> 7;                       // 0:i 1:f 2:g 3:o

    for (int s = 0; s < TSEQ; s++) {
        int t = dir ? (TSEQ - 1 - s) : s;
        // prefetch next timestep's xg (clamped; hidden under the dot product)
        int tn = dir ? max(t - 1, 0) : min(t + 1, TSEQ - 1);
        float xgn = __ldg(xg + xg_base + (size_t)tn * (BATCH * G4));

        float a0 = xgv, a1 = 0.f, a2 = 0.f, a3 = 0.f;
#pragma unroll
        for (int q = 0; q < RK / 4; q++) {       // register half: k = 4q..4q+3
            float4 hv = hs4[q];
            a0 += w[4 * q + 0] * hv.x;
            a1 += w[4 * q + 1] * hv.y;
            a2 += w[4 * q + 2] * hv.z;
            a3 += w[4 * q + 3] * hv.w;
        }
#pragma unroll
        for (int q = 0; q < SKQ; q++) {          // smem half: k = RK+4q..
            float4 hv = hs4[RK / 4 + q];
            float4 wv = ws4[q * G4 + j];
            a0 += wv.x * hv.x;
            a1 += wv.y * hv.y;
            a2 += wv.z * hv.z;
            a3 += wv.w * hv.w;
        }
        float pre = (a0 + a1) + (a2 + a3);

        float v = (gate == 2) ? ftanh_(pre) : fsig(pre);
        gs[j] = v;
        __syncthreads();

        if (j < HID) {
            float iv = gs[j];
            float fv = gs[j + HID];
            float gv = gs[j + 2 * HID];
            float ov = gs[j + 3 * HID];
            c = fv * c + iv * gv;
            float h = ov * ftanh_(c);
            hs[j] = h;
            outp[(size_t)t * outT + (size_t)b * outB + j] = h;
        }
        __syncthreads();
        xgv = xgn;
    }
}

// ---------------- launch ------------------------------------------------------
extern "C" void kernel_launch(void* const* d_in, const int* in_sizes, int n_in,
                              void* d_out, int out_size)
{
    const float* x        = (const float*)d_in[0];
    // d_in[1] = lengths (unused, as in the reference)
    const float* Wih_fw1  = (const float*)d_in[2];
    const float* Whh_fw1  = (const float*)d_in[3];
    const float* bih_fw1  = (const float*)d_in[4];
    const float* bhh_fw1  = (const float*)d_in[5];
    const float* Wih_bw1  = (const float*)d_in[6];
    const float* Whh_bw1  = (const float*)d_in[7];
    const float* bih_bw1  = (const float*)d_in[8];
    const float* bhh_bw1  = (const float*)d_in[9];
    const float* Wih_fw2  = (const float*)d_in[10];
    const float* Whh_fw2  = (const float*)d_in[11];
    const float* bih_fw2  = (const float*)d_in[12];
    const float* bhh_fw2  = (const float*)d_in[13];
    const float* Wih_bw2  = (const float*)d_in[14];
    const float* Whh_bw2  = (const float*)d_in[15];
    const float* bih_bw2  = (const float*)d_in[16];
    const float* bhh_bw2  = (const float*)d_in[17];
    float* out = (float*)d_out;

    float *xt, *xg, *out1;
    cudaGetSymbolAddress((void**)&xt,   g_xt);
    cudaGetSymbolAddress((void**)&xg,   g_xg);
    cudaGetSymbolAddress((void**)&out1, g_out1);

    cudaFuncSetAttribute(lstm_rec, cudaFuncAttributeMaxDynamicSharedMemorySize,
                         REC_SMEM_BYTES);

    const int M = TSEQ * BATCH;          // 65536

    // 1) transpose x -> [T,B,128]
    transpose_x<<<(TSEQ * BATCH * 32 + 255) / 256, 256>>>(
        (const float4*)x, (float4*)xt);

    // 2) layer-1 input projections (bias = bih + bhh folded in)
    dim3 gg(M / BM, G4 / BN);
    sgemm_bias<<<gg, 256>>>(xt, Wih_fw1, bih_fw1, bhh_fw1, xg,          M, G4, 128);
    sgemm_bias<<<gg, 256>>>(xt, Wih_bw1, bih_bw1, bhh_bw1, xg + XGHALF, M, G4, 128);

    // 3) layer-1 recurrence -> out1 [T,B,256]
    lstm_rec<<<dim3(BATCH, 2), 512, REC_SMEM_BYTES>>>(
        xg, Whh_fw1, Whh_bw1, out1, BATCH * 256, 256);

    // 4) layer-2 input projections (K = 256)
    sgemm_bias<<<gg, 256>>>(out1, Wih_fw2, bih_fw2, bhh_fw2, xg,          M, G4, 256);
    sgemm_bias<<<gg, 256>>>(out1, Wih_bw2, bih_bw2, bhh_bw2, xg + XGHALF, M, G4, 256);

    // 5) layer-2 recurrence -> d_out [B,T,256]
    lstm_rec<<<dim3(BATCH, 2), 512, REC_SMEM_BYTES>>>(
        xg, Whh_fw2, Whh_bw2, out, 256, TSEQ * 256);
}

// round 5
// speedup vs baseline: 1.1877x; 1.0992x over previous
#include <cuda_runtime.h>
#include <cuda_bf16.h>
#include <cstdint>

// Problem constants
#define TSEQ 1024
#define BATCH 64
#define HID 128
#define G4 512            // 4*HID
#define XGHALF (TSEQ*BATCH*G4)   // per-direction xg elements

// ---------------- scratch (static device globals; no allocations) -------------
__device__ float g_xt[TSEQ * BATCH * 128];        // x transposed to [T,B,128]
__device__ float g_xg[2 * TSEQ * BATCH * G4];     // [dir][T][B][512]
__device__ float g_out1[TSEQ * BATCH * 256];      // layer-1 output [T,B,256]

// ---------------- MUFU-free activations ---------------------------------------
// 2^y via magic round-to-int + degree-5 Taylor on |f|<=0.5 (rel err ~2e-6).
// Valid for |y| <= ~60 (callers clamp). All ops on the fma/alu pipes.
__device__ __forceinline__ float fexp2_fast(float y) {
    float t = y + 12582912.0f;                    // 1.5*2^23 round trick
    int   n = __float_as_int(t) - 0x4B400000;     // round(y)
    float f = y - (t - 12582912.0f);              // f in [-0.5, 0.5]
    float p =             1.3333558146e-3f;
    p = fmaf(p, f, 9.6181291076e-3f);
    p = fmaf(p, f, 5.5504108665e-2f);
    p = fmaf(p, f, 2.4022650696e-1f);
    p = fmaf(p, f, 6.9314718056e-1f);
    p = fmaf(p, f, 1.0f);
    return __int_as_float(__float_as_int(p) + (n << 23));
}
// 1/d via magic init + 3 Newton steps (exact to fp32 for d >= 1).
__device__ __forceinline__ float frcp_fast(float d) {
    float r = __int_as_float(0x7EF311C3 - __float_as_int(d));
    r = r * (2.0f - d * r);
    r = r * (2.0f - d * r);
    r = r * (2.0f - d * r);
    return r;
}
__device__ __forceinline__ float fsig_fast(float x) {
    x = fminf(fmaxf(x, -30.0f), 30.0f);
    float e = fexp2_fast(-1.4426950408889634f * x);   // e^{-x}
    return frcp_fast(1.0f + e);
}
__device__ __forceinline__ float ftanh_fast(float x) {
    x = fminf(fmaxf(x, -15.0f), 15.0f);
    float e = fexp2_fast(-2.8853900817779268f * x);   // e^{-2x}
    return fmaf(2.0f, frcp_fast(1.0f + e), -1.0f);
}

// ---------------- transpose x: [B,T,128] -> [T,B,128] -------------------------
__global__ void transpose_x(const float4* __restrict__ x, float4* __restrict__ xt) {
    int i = blockIdx.x * blockDim.x + threadIdx.x;   // over T*B*32 float4s
    if (i >= TSEQ * BATCH * 32) return;
    int t  = i >> 11;          // / (64*32)
    int r  = i & 2047;
    int b  = r >> 5;
    int k4 = r & 31;
    xt[i] = x[((size_t)b * TSEQ + t) * 32 + k4];
}

// ---------------- SGEMM: C[M,N] = A[M,K] * B[N,K]^T + bias1[n] + bias2[n] -----
// (R2 version — measured at the fp32 FFMA roofline; do not touch.)
#define BM 64
#define BN 64
#define BKK 16
__global__ __launch_bounds__(256) void sgemm_bias(
    const float* __restrict__ A, const float* __restrict__ B,
    const float* __restrict__ bias1, const float* __restrict__ bias2,
    float* __restrict__ C, int M, int N, int K)
{
    __shared__ float As[BKK][BM + 4];
    __shared__ float Bs[BKK][BN + 4];

    int tid = threadIdx.x;
    int tx = tid & 15;
    int ty = tid >> 4;
    int block_m = blockIdx.x * BM;
    int block_n = blockIdx.y * BN;

    int lr = tid >> 2;
    int lc = (tid & 3) * 4;

    const float* Ab = A + (size_t)(block_m + lr) * K + lc;
    const float* Bb = B + (size_t)(block_n + lr) * K + lc;

    float acc[4][4];
#pragma unroll
    for (int i = 0; i < 4; i++)
#pragma unroll
        for (int jj = 0; jj < 4; jj++) acc[i][jj] = 0.f;

    for (int k0 = 0; k0 < K; k0 += BKK) {
        float4 av = *(const float4*)(Ab + k0);
        float4 bv = *(const float4*)(Bb + k0);
        As[lc + 0][lr] = av.x; As[lc + 1][lr] = av.y;
        As[lc + 2][lr] = av.z; As[lc + 3][lr] = av.w;
        Bs[lc + 0][lr] = bv.x; Bs[lc + 1][lr] = bv.y;
        Bs[lc + 2][lr] = bv.z; Bs[lc + 3][lr] = bv.w;
        __syncthreads();
#pragma unroll
        for (int k = 0; k < BKK; k++) {
            float4 a = *(const float4*)&As[k][ty * 4];
            float4 b = *(const float4*)&Bs[k][tx * 4];
            acc[0][0] += a.x * b.x; acc[0][1] += a.x * b.y;
            acc[0][2] += a.x * b.z; acc[0][3] += a.x * b.w;
            acc[1][0] += a.y * b.x; acc[1][1] += a.y * b.y;
            acc[1][2] += a.y * b.z; acc[1][3] += a.y * b.w;
            acc[2][0] += a.z * b.x; acc[2][1] += a.z * b.y;
            acc[2][2] += a.z * b.z; acc[2][3] += a.z * b.w;
            acc[3][0] += a.w * b.x; acc[3][1] += a.w * b.y;
            acc[3][2] += a.w * b.z; acc[3][3] += a.w * b.w;
        }
        __syncthreads();
    }

#pragma unroll
    for (int i = 0; i < 4; i++) {
        size_t row = (size_t)(block_m + ty * 4 + i);
#pragma unroll
        for (int jj = 0; jj < 4; jj++) {
            int n = block_n + tx * 4 + jj;
            C[row * N + n] = acc[i][jj] + __ldg(&bias1[n]) + __ldg(&bias2[n]);
        }
    }
}

// ---------------- recurrent LSTM scan: one CTA per (batch, direction) ---------
// 512 threads; thread j owns gate row j (gate = j>>7 in {i,f,g,o}).
// Whh row j: cols 0..RK-1 in registers, cols RK..127 in smem (transposed quads).
#define RK 80
#define SKQ ((128 - RK) / 4)           // 12 smem quads per row
#define REC_SMEM_FLOATS ((128 - RK) * G4 + HID + G4)
#define REC_SMEM_BYTES (REC_SMEM_FLOATS * 4)

__global__ __launch_bounds__(512, 1) void lstm_rec(
    const float* __restrict__ xg,        // [dir][T][B][512]
    const float* __restrict__ Whh0,      // fw weights [512][128]
    const float* __restrict__ Whh1,      // bw weights [512][128]
    float* __restrict__ out,             // h output
    int outT, int outB)                  // strides (floats) for t and b
{
    extern __shared__ float sm[];
    float4* ws4 = (float4*)sm;                   // SKQ*512 float4 (cols RK..127)
    float* hs = sm + (128 - RK) * G4;            // 128 (16B aligned)
    float* gs = hs + HID;                        // 512

    int j   = threadIdx.x;
    int b   = blockIdx.x;
    int dir = blockIdx.y;
    const float* Whh = dir ? Whh1 : Whh0;

    const float4* Wr4 = (const float4*)(Whh + (size_t)j * 128);
    float w[RK];
#pragma unroll
    for (int k4 = 0; k4 < RK / 4; k4++) {
        float4 v = Wr4[k4];
        w[4 * k4 + 0] = v.x; w[4 * k4 + 1] = v.y;
        w[4 * k4 + 2] = v.z; w[4 * k4 + 3] = v.w;
    }
#pragma unroll
    for (int q = 0; q < SKQ; q++)
        ws4[q * G4 + j] = Wr4[RK / 4 + q];

    if (j < HID) hs[j] = 0.f;
    float c = 0.f;
    __syncthreads();

    const float4* hs4 = (const float4*)hs;
    size_t xg_base = (size_t)dir * XGHALF + (size_t)b * G4 + j;
    int t0 = dir ? (TSEQ - 1) : 0;
    float xgv = __ldg(xg + xg_base + (size_t)t0 * (BATCH * G4));
    float* outp = out + dir * HID;
    bool isg = ((j >> 7) == 2);              // tanh gate?

    for (int s = 0; s < TSEQ; s++) {
        int t = dir ? (TSEQ - 1 - s) : s;
        int tn = dir ? max(t - 1, 0) : min(t + 1, TSEQ - 1);
        float xgn = __ldg(xg + xg_base + (size_t)tn * (BATCH * G4));

        float a0 = xgv, a1 = 0.f, a2 = 0.f, a3 = 0.f;
#pragma unroll
        for (int q = 0; q < RK / 4; q++) {       // register half
            float4 hv = hs4[q];
            a0 += w[4 * q + 0] * hv.x;
            a1 += w[4 * q + 1] * hv.y;
            a2 += w[4 * q + 2] * hv.z;
            a3 += w[4 * q + 3] * hv.w;
        }
#pragma unroll
        for (int q = 0; q < SKQ; q++) {          // smem half
            float4 hv = hs4[RK / 4 + q];
            float4 wv = ws4[q * G4 + j];
            a0 += wv.x * hv.x;
            a1 += wv.y * hv.y;
            a2 += wv.z * hv.z;
            a3 += wv.w * hv.w;
        }
        float pre = (a0 + a1) + (a2 + a3);

        // unified MUFU-free activation: tanh(x) = 2*sig(2x)-1
        float xs = isg ? pre + pre : pre;
        float sv = fsig_fast(xs);
        float v  = isg ? fmaf(2.0f, sv, -1.0f) : sv;
        gs[j] = v;
        __syncthreads();

        if (j < HID) {
            float iv = gs[j];
            float fv = gs[j + HID];
            float gv = gs[j + 2 * HID];
            float ov = gs[j + 3 * HID];
            c = fmaf(fv, c, iv * gv);
            float h = ov * ftanh_fast(c);
            hs[j] = h;
            outp[(size_t)t * outT + (size_t)b * outB + j] = h;
        }
        __syncthreads();
        xgv = xgn;
    }
}

// ---------------- launch ------------------------------------------------------
extern "C" void kernel_launch(void* const* d_in, const int* in_sizes, int n_in,
                              void* d_out, int out_size)
{
    const float* x        = (const float*)d_in[0];
    // d_in[1] = lengths (unused, as in the reference)
    const float* Wih_fw1  = (const float*)d_in[2];
    const float* Whh_fw1  = (const float*)d_in[3];
    const float* bih_fw1  = (const float*)d_in[4];
    const float* bhh_fw1  = (const float*)d_in[5];
    const float* Wih_bw1  = (const float*)d_in[6];
    const float* Whh_bw1  = (const float*)d_in[7];
    const float* bih_bw1  = (const float*)d_in[8];
    const float* bhh_bw1  = (const float*)d_in[9];
    const float* Wih_fw2  = (const float*)d_in[10];
    const float* Whh_fw2  = (const float*)d_in[11];
    const float* bih_fw2  = (const float*)d_in[12];
    const float* bhh_fw2  = (const float*)d_in[13];
    const float* Wih_bw2  = (const float*)d_in[14];
    const float* Whh_bw2  = (const float*)d_in[15];
    const float* bih_bw2  = (const float*)d_in[16];
    const float* bhh_bw2  = (const float*)d_in[17];
    float* out = (float*)d_out;

    float *xt, *xg, *out1;
    cudaGetSymbolAddress((void**)&xt,   g_xt);
    cudaGetSymbolAddress((void**)&xg,   g_xg);
    cudaGetSymbolAddress((void**)&out1, g_out1);

    cudaFuncSetAttribute(lstm_rec, cudaFuncAttributeMaxDynamicSharedMemorySize,
                         REC_SMEM_BYTES);

    const int M = TSEQ * BATCH;          // 65536

    // 1) transpose x -> [T,B,128]
    transpose_x<<<(TSEQ * BATCH * 32 + 255) / 256, 256>>>(
        (const float4*)x, (float4*)xt);

    // 2) layer-1 input projections (bias = bih + bhh folded in)
    dim3 gg(M / BM, G4 / BN);
    sgemm_bias<<<gg, 256>>>(xt, Wih_fw1, bih_fw1, bhh_fw1, xg,          M, G4, 128);
    sgemm_bias<<<gg, 256>>>(xt, Wih_bw1, bih_bw1, bhh_bw1, xg + XGHALF, M, G4, 128);

    // 3) layer-1 recurrence -> out1 [T,B,256]
    lstm_rec<<<dim3(BATCH, 2), 512, REC_SMEM_BYTES>>>(
        xg, Whh_fw1, Whh_bw1, out1, BATCH * 256, 256);

    // 4) layer-2 input projections (K = 256)
    sgemm_bias<<<gg, 256>>>(out1, Wih_fw2, bih_fw2, bhh_fw2, xg,          M, G4, 256);
    sgemm_bias<<<gg, 256>>>(out1, Wih_bw2, bih_bw2, bhh_bw2, xg + XGHALF, M, G4, 256);

    // 5) layer-2 recurrence -> d_out [B,T,256]
    lstm_rec<<<dim3(BATCH, 2), 512, REC_SMEM_BYTES>>>(
        xg, Whh_fw2, Whh_bw2, out, 256, TSEQ * 256);
}